// round 1
// baseline (speedup 1.0000x reference)
#include <cuda_runtime.h>
#include <math.h>

// Shapes (fixed by the problem)
#define B_  16
#define C_  256
#define H_  96
#define W_  96
#define G_  4
#define KK  3
#define RED 4
#define CH  (C_ / RED)        // 64
#define PLANE (H_ * W_)       // 9216
#define BC (B_ * C_)          // 4096

// Scratch (allocation-free rule -> __device__ globals)
__device__ float g_pooled[B_ * C_ * 9];   // (B,C,3,3)
__device__ float g_gmean [B_ * C_];       // (B,C)
__device__ float g_weight[B_ * C_ * 9];   // dynamic depthwise kernels
__device__ float g_bias  [B_ * C_];       // dynamic bias

// ---------------------------------------------------------------------------
// Kernel 1: per-(b,c) plane -> 3x3 block means (32x32 blocks) + global mean
// grid = BC blocks, 256 threads. Coalesced float4 reads.
// ---------------------------------------------------------------------------
__global__ __launch_bounds__(256) void pool_kernel(const float* __restrict__ x) {
    int bc = blockIdx.x;
    const float4* xp = reinterpret_cast<const float4*>(x + (size_t)bc * PLANE);
    __shared__ float bins[9];
    int tid = threadIdx.x;
    if (tid < 9) bins[tid] = 0.f;
    __syncthreads();

    // 3 row-bands of 32 rows; each band = 768 float4 (24 float4 per row)
    #pragma unroll
    for (int band = 0; band < 3; band++) {
        float a0 = 0.f, a1 = 0.f, a2 = 0.f;
        #pragma unroll
        for (int j = 0; j < 3; j++) {
            int idx = band * 768 + tid + j * 256;
            float4 v = xp[idx];
            float s = (v.x + v.y) + (v.z + v.w);
            int kx = (idx % 24) / 8;        // column block (each float4 fully inside one)
            if (kx == 0) a0 += s; else if (kx == 1) a1 += s; else a2 += s;
        }
        #pragma unroll
        for (int o = 16; o > 0; o >>= 1) {
            a0 += __shfl_down_sync(0xffffffffu, a0, o);
            a1 += __shfl_down_sync(0xffffffffu, a1, o);
            a2 += __shfl_down_sync(0xffffffffu, a2, o);
        }
        if ((tid & 31) == 0) {
            atomicAdd(&bins[band * 3 + 0], a0);
            atomicAdd(&bins[band * 3 + 1], a1);
            atomicAdd(&bins[band * 3 + 2], a2);
        }
    }
    __syncthreads();
    if (tid < 9) g_pooled[bc * 9 + tid] = bins[tid] * (1.f / 1024.f);
    if (tid == 0) {
        float t = 0.f;
        #pragma unroll
        for (int i = 0; i < 9; i++) t += bins[i];
        g_gmean[bc] = t * (1.f / (float)PLANE);
    }
}

// ---------------------------------------------------------------------------
// Kernel 2: proj + softmax + mixdown.
// grid = (10 positions, B). 256 threads (one per channel c).
// pos 0..8 -> dynamic 3x3 kernel entry; pos 9 -> dynamic bias (global mean).
// ---------------------------------------------------------------------------
__global__ __launch_bounds__(256) void proj_kernel(
    const float* __restrict__ w1, const float* __restrict__ b1,
    const float* __restrict__ bn_g, const float* __restrict__ bn_b,
    const float* __restrict__ bn_m, const float* __restrict__ bn_v,
    const float* __restrict__ w2, const float* __restrict__ b2,
    const float* __restrict__ w_k, const float* __restrict__ b_k)
{
    int pos = blockIdx.x;   // 0..9
    int b   = blockIdx.y;   // 0..15
    int tid = threadIdx.x;
    int c   = tid;

    __shared__ float t_s[C_];
    __shared__ float hpart[4][CH];
    __shared__ float h_s[CH];

    t_s[c] = (pos < 9) ? g_pooled[(b * C_ + c) * 9 + pos] : g_gmean[b * C_ + c];
    __syncthreads();

    // h[o] = b1[o] + sum_c w1[o,c] * t[c]   (split-K over 4 thread groups)
    {
        int o = tid & 63, part = tid >> 6;
        const float* wr = w1 + o * C_ + part * 64;
        const float* ts = t_s + part * 64;
        float acc = 0.f;
        #pragma unroll 8
        for (int k = 0; k < 64; k++) acc = fmaf(wr[k], ts[k], acc);
        hpart[part][o] = acc;
    }
    __syncthreads();
    if (tid < CH) {
        float h = hpart[0][tid] + hpart[1][tid] + hpart[2][tid] + hpart[3][tid] + b1[tid];
        h = (h - bn_m[tid]) * (bn_g[tid] * rsqrtf(bn_v[tid] + 1e-5f)) + bn_b[tid];
        h = 0.5f * h * (1.0f + erff(h * 0.70710678118654752f));  // exact gelu
        h_s[tid] = h;
    }
    __syncthreads();

    // v[g] = b2[g*C+c] + w2[g*C+c, :] . h
    float v[G_];
    #pragma unroll
    for (int g = 0; g < G_; g++) {
        const float* wr2 = w2 + (size_t)(g * C_ + c) * CH;
        float a = b2[g * C_ + c];
        #pragma unroll 8
        for (int k = 0; k < CH; k++) a = fmaf(wr2[k], h_s[k], a);
        v[g] = a;
    }
    // softmax over g
    float m = fmaxf(fmaxf(v[0], v[1]), fmaxf(v[2], v[3]));
    float e[G_]; float s = 0.f;
    #pragma unroll
    for (int g = 0; g < G_; g++) { e[g] = expf(v[g] - m); s += e[g]; }
    float inv = 1.f / s;

    if (pos < 9) {
        float w = 0.f;
        #pragma unroll
        for (int g = 0; g < G_; g++) w = fmaf(e[g] * inv, w_k[(g * C_ + c) * 9 + pos], w);
        g_weight[(b * C_ + c) * 9 + pos] = w;
    } else {
        float bb = 0.f;
        #pragma unroll
        for (int g = 0; g < G_; g++) bb = fmaf(e[g] * inv, b_k[g * C_ + c], bb);
        g_bias[b * C_ + c] = bb;
    }
}

// ---------------------------------------------------------------------------
// Kernel 3: depthwise 3x3 conv, per-(b,c) dynamic weights + bias, SAME pad.
// grid = BC blocks, 256 threads, whole padded plane in smem.
// ---------------------------------------------------------------------------
#define SW 104   // smem row stride (floats); interior starts at col 4 (16B aligned)

__global__ __launch_bounds__(256) void conv_kernel(const float* __restrict__ x,
                                                   float* __restrict__ out)
{
    __shared__ float s[98 * SW];
    int bc  = blockIdx.x;
    int tid = threadIdx.x;
    const float4* xp4 = reinterpret_cast<const float4*>(x + (size_t)bc * PLANE);

    // zero (covers the halo)
    for (int i = tid; i < 98 * SW; i += 256) s[i] = 0.f;
    __syncthreads();

    // load interior: input row r -> smem row r+1; input col ci -> smem col ci+4
    #pragma unroll
    for (int j = 0; j < 9; j++) {
        int idx = tid + j * 256;                 // 2304 float4 total
        float4 v = xp4[idx];
        int r  = idx / 24;
        int c4 = (idx % 24) * 4;
        *reinterpret_cast<float4*>(&s[(r + 1) * SW + 4 + c4]) = v;
    }

    float w[9];
    #pragma unroll
    for (int i = 0; i < 9; i++) w[i] = __ldg(&g_weight[bc * 9 + i]);
    float bb = __ldg(&g_bias[bc]);
    __syncthreads();

    float* op = out + (size_t)bc * PLANE;
    #pragma unroll
    for (int j = 0; j < 9; j++) {
        int item = tid + j * 256;                // 2304 strips of 4 outputs
        int r  = item / 24;
        int c0 = (item % 24) * 4;
        float o0 = bb, o1 = bb, o2 = bb, o3 = bb;
        #pragma unroll
        for (int k = 0; k < 3; k++) {
            // input row r-1+k -> smem row r+k ; cols c0-1..c0+4 -> smem c0+3..c0+8
            int rb = (r + k) * SW + 4 + c0;
            float  l  = s[rb - 1];
            float4 m4 = *reinterpret_cast<const float4*>(&s[rb]);
            float  rr = s[rb + 4];
            float w0 = w[k * 3 + 0], w1v = w[k * 3 + 1], w2v = w[k * 3 + 2];
            o0 = fmaf(w0, l,    fmaf(w1v, m4.x, fmaf(w2v, m4.y, o0)));
            o1 = fmaf(w0, m4.x, fmaf(w1v, m4.y, fmaf(w2v, m4.z, o1)));
            o2 = fmaf(w0, m4.y, fmaf(w1v, m4.z, fmaf(w2v, m4.w, o2)));
            o3 = fmaf(w0, m4.z, fmaf(w1v, m4.w, fmaf(w2v, rr,   o3)));
        }
        *reinterpret_cast<float4*>(&op[r * W_ + c0]) = make_float4(o0, o1, o2, o3);
    }
}

// ---------------------------------------------------------------------------
// Launch. Inputs (metadata order): x, w_k, b_k, w1, b1, bn_g, bn_b, bn_m,
// bn_v, w2, b2. Output: float32 (B,C,H,W).
// ---------------------------------------------------------------------------
extern "C" void kernel_launch(void* const* d_in, const int* in_sizes, int n_in,
                              void* d_out, int out_size)
{
    const float* x    = (const float*)d_in[0];
    const float* w_k  = (const float*)d_in[1];
    const float* b_k  = (const float*)d_in[2];
    const float* w1   = (const float*)d_in[3];
    const float* b1   = (const float*)d_in[4];
    const float* bn_g = (const float*)d_in[5];
    const float* bn_b = (const float*)d_in[6];
    const float* bn_m = (const float*)d_in[7];
    const float* bn_v = (const float*)d_in[8];
    const float* w2   = (const float*)d_in[9];
    const float* b2   = (const float*)d_in[10];
    float* out = (float*)d_out;

    pool_kernel<<<BC, 256>>>(x);
    dim3 pg(10, B_);
    proj_kernel<<<pg, 256>>>(w1, b1, bn_g, bn_b, bn_m, bn_v, w2, b2, w_k, b_k);
    conv_kernel<<<BC, 256>>>(x, out);
}

// round 2
// speedup vs baseline: 1.0196x; 1.0196x over previous
#include <cuda_runtime.h>
#include <math.h>

// Shapes (fixed by the problem)
#define B_  16
#define C_  256
#define H_  96
#define W_  96
#define G_  4
#define KK  3
#define RED 4
#define CH  (C_ / RED)        // 64
#define PLANE (H_ * W_)       // 9216
#define BC (B_ * C_)          // 4096

// Scratch (allocation-free rule -> __device__ globals)
__device__ float g_pooled[B_ * C_ * 9];   // (B,C,3,3)
__device__ float g_gmean [B_ * C_];       // (B,C)
__device__ float g_weight[B_ * C_ * 9];   // dynamic depthwise kernels
__device__ float g_bias  [B_ * C_];       // dynamic bias

// ---------------------------------------------------------------------------
// Kernel 1: per-(b,c) plane -> 3x3 block means (32x32 blocks) + global mean
// grid = BC blocks, 256 threads. All 9 float4 loads issued up-front (MLP=9).
// ---------------------------------------------------------------------------
__global__ __launch_bounds__(256) void pool_kernel(const float* __restrict__ x) {
    int bc = blockIdx.x;
    const float4* xp = reinterpret_cast<const float4*>(x + (size_t)bc * PLANE);
    __shared__ float bins[9];
    int tid = threadIdx.x;
    if (tid < 9) bins[tid] = 0.f;
    __syncthreads();

    // all loads first: maximum MLP
    float4 v[9];
    #pragma unroll
    for (int j = 0; j < 9; j++) v[j] = xp[tid + j * 256];

    // accumulate: band = j/3 (uniform per unroll step); kx from (tid+16j)%24
    float a[3][3];
    #pragma unroll
    for (int b2 = 0; b2 < 3; b2++)
        #pragma unroll
        for (int k = 0; k < 3; k++) a[b2][k] = 0.f;

    #pragma unroll
    for (int j = 0; j < 9; j++) {
        float s = (v[j].x + v[j].y) + (v[j].z + v[j].w);
        int band = j / 3;                       // compile-time
        int kx = ((tid + 16 * j) % 24) / 8;     // runtime, but static acc index via if-chain
        if (kx == 0) a[band][0] += s; else if (kx == 1) a[band][1] += s; else a[band][2] += s;
    }

    #pragma unroll
    for (int b2 = 0; b2 < 3; b2++)
        #pragma unroll
        for (int k = 0; k < 3; k++) {
            float t = a[b2][k];
            #pragma unroll
            for (int o = 16; o > 0; o >>= 1) t += __shfl_down_sync(0xffffffffu, t, o);
            if ((tid & 31) == 0) atomicAdd(&bins[b2 * 3 + k], t);
        }
    __syncthreads();
    if (tid < 9) g_pooled[bc * 9 + tid] = bins[tid] * (1.f / 1024.f);
    if (tid == 0) {
        float t = 0.f;
        #pragma unroll
        for (int i = 0; i < 9; i++) t += bins[i];
        g_gmean[bc] = t * (1.f / (float)PLANE);
    }
}

// ---------------------------------------------------------------------------
// Kernel 2: proj + softmax + mixdown.
// grid = (10 positions, B). 256 threads (one per channel c).
// ---------------------------------------------------------------------------
__global__ __launch_bounds__(256) void proj_kernel(
    const float* __restrict__ w1, const float* __restrict__ b1,
    const float* __restrict__ bn_g, const float* __restrict__ bn_b,
    const float* __restrict__ bn_m, const float* __restrict__ bn_v,
    const float* __restrict__ w2, const float* __restrict__ b2,
    const float* __restrict__ w_k, const float* __restrict__ b_k)
{
    int pos = blockIdx.x;   // 0..9
    int b   = blockIdx.y;   // 0..15
    int tid = threadIdx.x;
    int c   = tid;

    __shared__ float t_s[C_];
    __shared__ float hpart[4][CH];
    __shared__ float h_s[CH];

    t_s[c] = (pos < 9) ? g_pooled[(b * C_ + c) * 9 + pos] : g_gmean[b * C_ + c];
    __syncthreads();

    // h[o] = b1[o] + sum_c w1[o,c] * t[c]   (split-K over 4 thread groups)
    {
        int o = tid & 63, part = tid >> 6;
        const float* wr = w1 + o * C_ + part * 64;
        const float* ts = t_s + part * 64;
        float acc = 0.f;
        #pragma unroll 8
        for (int k = 0; k < 64; k++) acc = fmaf(wr[k], ts[k], acc);
        hpart[part][o] = acc;
    }
    __syncthreads();
    if (tid < CH) {
        float h = hpart[0][tid] + hpart[1][tid] + hpart[2][tid] + hpart[3][tid] + b1[tid];
        h = (h - bn_m[tid]) * (bn_g[tid] * rsqrtf(bn_v[tid] + 1e-5f)) + bn_b[tid];
        h = 0.5f * h * (1.0f + erff(h * 0.70710678118654752f));  // exact gelu
        h_s[tid] = h;
    }
    __syncthreads();

    // v[g] = b2[g*C+c] + w2[g*C+c, :] . h
    float v[G_];
    #pragma unroll
    for (int g = 0; g < G_; g++) {
        const float* wr2 = w2 + (size_t)(g * C_ + c) * CH;
        float a = b2[g * C_ + c];
        #pragma unroll 8
        for (int k = 0; k < CH; k++) a = fmaf(wr2[k], h_s[k], a);
        v[g] = a;
    }
    // softmax over g
    float m = fmaxf(fmaxf(v[0], v[1]), fmaxf(v[2], v[3]));
    float e[G_]; float s = 0.f;
    #pragma unroll
    for (int g = 0; g < G_; g++) { e[g] = expf(v[g] - m); s += e[g]; }
    float inv = 1.f / s;

    if (pos < 9) {
        float w = 0.f;
        #pragma unroll
        for (int g = 0; g < G_; g++) w = fmaf(e[g] * inv, w_k[(g * C_ + c) * 9 + pos], w);
        g_weight[(b * C_ + c) * 9 + pos] = w;
    } else {
        float bb = 0.f;
        #pragma unroll
        for (int g = 0; g < G_; g++) bb = fmaf(e[g] * inv, b_k[g * C_ + c], bb);
        g_bias[b * C_ + c] = bb;
    }
}

// ---------------------------------------------------------------------------
// Kernel 3: depthwise 3x3 conv, per-(b,c) dynamic weights + bias, SAME pad.
// grid = (3 tiles, BC planes), 256 threads. Each block: 32 output rows
// (+2 halo rows) of one (b,c) plane in 13.8KB smem -> 8 CTAs/SM.
// ---------------------------------------------------------------------------
#define SW 104          // smem row stride (floats); interior starts at col 4
#define TROWS 32        // output rows per block
#define SROWS (TROWS+2) // smem rows (34)

__global__ __launch_bounds__(256) void conv_kernel(const float* __restrict__ x,
                                                   float* __restrict__ out)
{
    __shared__ float s[SROWS * SW];
    int tile = blockIdx.x;          // 0..2
    int bc   = blockIdx.y;          // 0..4095
    int tid  = threadIdx.x;
    int r0   = tile * TROWS;
    const float4* xp4 = reinterpret_cast<const float4*>(x + (size_t)bc * PLANE);

    // zero everything (covers halo rows/cols)
    #pragma unroll
    for (int j = 0; j < 14; j++) {
        int i = tid + j * 256;
        if (i < SROWS * SW) s[i] = 0.f;
    }
    __syncthreads();

    // load rows r0-1 .. r0+32 -> smem rows 0..33, cols shifted by +4
    // 34 rows x 24 float4 = 816 float4
    #pragma unroll
    for (int j = 0; j < 4; j++) {
        int idx = tid + j * 256;
        if (idx < SROWS * 24) {
            int sr = idx / 24;
            int c4 = idx % 24;
            int ir = r0 - 1 + sr;
            if (ir >= 0 && ir < H_) {
                float4 v = xp4[ir * 24 + c4];
                *reinterpret_cast<float4*>(&s[sr * SW + 4 + c4 * 4]) = v;
            }
        }
    }

    float w[9];
    #pragma unroll
    for (int i = 0; i < 9; i++) w[i] = __ldg(&g_weight[bc * 9 + i]);
    float bb = __ldg(&g_bias[bc]);
    __syncthreads();

    float* op = out + (size_t)bc * PLANE + (size_t)r0 * W_;
    // 32 rows x 24 strips = 768 strips, 3 per thread
    #pragma unroll
    for (int j = 0; j < 3; j++) {
        int item = tid + j * 256;
        int r  = item / 24;                 // local output row 0..31
        int c0 = (item % 24) * 4;
        float o0 = bb, o1 = bb, o2 = bb, o3 = bb;
        #pragma unroll
        for (int k = 0; k < 3; k++) {
            // output row r needs input rows r0+r-1..r0+r+1 = smem rows r..r+2
            int rb = (r + k) * SW + 4 + c0;
            float  l  = s[rb - 1];
            float4 m4 = *reinterpret_cast<const float4*>(&s[rb]);
            float  rr = s[rb + 4];
            float w0 = w[k * 3 + 0], w1v = w[k * 3 + 1], w2v = w[k * 3 + 2];
            o0 = fmaf(w0, l,    fmaf(w1v, m4.x, fmaf(w2v, m4.y, o0)));
            o1 = fmaf(w0, m4.x, fmaf(w1v, m4.y, fmaf(w2v, m4.z, o1)));
            o2 = fmaf(w0, m4.y, fmaf(w1v, m4.z, fmaf(w2v, m4.w, o2)));
            o3 = fmaf(w0, m4.z, fmaf(w1v, m4.w, fmaf(w2v, rr,   o3)));
        }
        *reinterpret_cast<float4*>(&op[r * W_ + c0]) = make_float4(o0, o1, o2, o3);
    }
}

// ---------------------------------------------------------------------------
// Launch. Inputs (metadata order): x, w_k, b_k, w1, b1, bn_g, bn_b, bn_m,
// bn_v, w2, b2. Output: float32 (B,C,H,W).
// ---------------------------------------------------------------------------
extern "C" void kernel_launch(void* const* d_in, const int* in_sizes, int n_in,
                              void* d_out, int out_size)
{
    const float* x    = (const float*)d_in[0];
    const float* w_k  = (const float*)d_in[1];
    const float* b_k  = (const float*)d_in[2];
    const float* w1   = (const float*)d_in[3];
    const float* b1   = (const float*)d_in[4];
    const float* bn_g = (const float*)d_in[5];
    const float* bn_b = (const float*)d_in[6];
    const float* bn_m = (const float*)d_in[7];
    const float* bn_v = (const float*)d_in[8];
    const float* w2   = (const float*)d_in[9];
    const float* b2   = (const float*)d_in[10];
    float* out = (float*)d_out;

    pool_kernel<<<BC, 256>>>(x);
    dim3 pg(10, B_);
    proj_kernel<<<pg, 256>>>(w1, b1, bn_g, bn_b, bn_m, bn_v, w2, b2, w_k, b_k);
    dim3 cg(3, BC);
    conv_kernel<<<cg, 256>>>(x, out);
}

// round 3
// speedup vs baseline: 1.4333x; 1.4058x over previous
#include <cuda_runtime.h>
#include <math.h>

#define B_  16
#define C_  256
#define H_  96
#define W_  96
#define G_  4
#define KK  3
#define RED 4
#define CH  (C_ / RED)        // 64
#define PLANE (H_ * W_)       // 9216
#define BC (B_ * C_)          // 4096

// Scratch (allocation-free rule -> __device__ globals)
__device__ float g_pooled[B_ * C_ * 9];
__device__ float g_gmean [B_ * C_];
__device__ float g_weight[B_ * C_ * 9];
__device__ float g_bias  [B_ * C_];
__device__ float g_w1t[C_ * CH];        // w1t[k][o] = w1[o][k]   (256 x 64)
__device__ float g_w2t[CH * C_ * G_];   // w2t[k][gc] = w2[gc][k] (64 x 1024)

// ---------------------------------------------------------------------------
// Kernel 0: transpose w1 (64x256 -> 256x64) and w2 (1024x64 -> 64x1024).
// Coalesced writes; one-time tiny cost. grid=80 blocks x 256 thr.
// ---------------------------------------------------------------------------
__global__ __launch_bounds__(256) void transpose_kernel(const float* __restrict__ w1,
                                                        const float* __restrict__ w2)
{
    int idx = blockIdx.x * 256 + threadIdx.x;
    if (idx < C_ * CH) {
        int k = idx / CH, o = idx % CH;         // write w1t[k*64+o]
        g_w1t[idx] = w1[o * C_ + k];
    }
    int idx2 = idx;                             // 0 .. 20479 covers 64*1024 via grid 80*256=20480... need 65536
    // w2t: 65536 elements -> iterate
    for (int i = idx2; i < CH * C_ * G_; i += gridDim.x * 256) {
        int k = i / (C_ * G_), gc = i % (C_ * G_);
        g_w2t[i] = w2[gc * CH + k];
    }
}

// ---------------------------------------------------------------------------
// Kernel 1: per-(b,c) plane -> 3x3 block means + global mean (R1 form).
// ---------------------------------------------------------------------------
__global__ __launch_bounds__(256) void pool_kernel(const float* __restrict__ x) {
    int bc = blockIdx.x;
    const float4* xp = reinterpret_cast<const float4*>(x + (size_t)bc * PLANE);
    __shared__ float bins[9];
    int tid = threadIdx.x;
    if (tid < 9) bins[tid] = 0.f;
    __syncthreads();

    #pragma unroll
    for (int band = 0; band < 3; band++) {
        float a0 = 0.f, a1 = 0.f, a2 = 0.f;
        #pragma unroll
        for (int j = 0; j < 3; j++) {
            int idx = band * 768 + tid + j * 256;
            float4 v = xp[idx];
            float s = (v.x + v.y) + (v.z + v.w);
            int kx = (idx % 24) / 8;
            if (kx == 0) a0 += s; else if (kx == 1) a1 += s; else a2 += s;
        }
        #pragma unroll
        for (int o = 16; o > 0; o >>= 1) {
            a0 += __shfl_down_sync(0xffffffffu, a0, o);
            a1 += __shfl_down_sync(0xffffffffu, a1, o);
            a2 += __shfl_down_sync(0xffffffffu, a2, o);
        }
        if ((tid & 31) == 0) {
            atomicAdd(&bins[band * 3 + 0], a0);
            atomicAdd(&bins[band * 3 + 1], a1);
            atomicAdd(&bins[band * 3 + 2], a2);
        }
    }
    __syncthreads();
    if (tid < 9) g_pooled[bc * 9 + tid] = bins[tid] * (1.f / 1024.f);
    if (tid == 0) {
        float t = 0.f;
        #pragma unroll
        for (int i = 0; i < 9; i++) t += bins[i];
        g_gmean[bc] = t * (1.f / (float)PLANE);
    }
}

// ---------------------------------------------------------------------------
// Kernel 2: proj + softmax + mixdown, with COALESCED transposed weights.
// grid = (10 positions, B). 256 threads (one per channel c).
// ---------------------------------------------------------------------------
__global__ __launch_bounds__(256) void proj_kernel(
    const float* __restrict__ b1,
    const float* __restrict__ bn_g, const float* __restrict__ bn_b,
    const float* __restrict__ bn_m, const float* __restrict__ bn_v,
    const float* __restrict__ b2,
    const float* __restrict__ w_k, const float* __restrict__ b_k)
{
    int pos = blockIdx.x;   // 0..9
    int b   = blockIdx.y;   // 0..15
    int tid = threadIdx.x;
    int c   = tid;

    __shared__ float t_s[C_];
    __shared__ float hpart[4][CH];
    __shared__ float h_s[CH];

    t_s[c] = (pos < 9) ? g_pooled[(b * C_ + c) * 9 + pos] : g_gmean[b * C_ + c];
    __syncthreads();

    // h[o] = b1[o] + sum_k w1t[k][o] * t[k]  (split-K over 4 groups, coalesced)
    {
        int o = tid & 63, part = tid >> 6;
        const float* wt = g_w1t + part * 64 * CH + o;   // w1t[(part*64+k)*64+o]
        const float* ts = t_s + part * 64;
        float acc = 0.f;
        #pragma unroll 8
        for (int k = 0; k < 64; k++) acc = fmaf(wt[k * CH], ts[k], acc);
        hpart[part][o] = acc;
    }
    __syncthreads();
    if (tid < CH) {
        float h = hpart[0][tid] + hpart[1][tid] + hpart[2][tid] + hpart[3][tid] + b1[tid];
        h = (h - bn_m[tid]) * (bn_g[tid] * rsqrtf(bn_v[tid] + 1e-5f)) + bn_b[tid];
        h = 0.5f * h * (1.0f + erff(h * 0.70710678118654752f));  // exact gelu
        h_s[tid] = h;
    }
    __syncthreads();

    // v[g] = b2[g*C+c] + sum_k w2t[k][g*C+c] * h[k]  (coalesced over c)
    float v[G_];
    #pragma unroll
    for (int g = 0; g < G_; g++) v[g] = b2[g * C_ + c];
    #pragma unroll 8
    for (int k = 0; k < CH; k++) {
        float h = h_s[k];
        const float* row = g_w2t + (size_t)k * (C_ * G_) + c;
        #pragma unroll
        for (int g = 0; g < G_; g++) v[g] = fmaf(row[g * C_], h, v[g]);
    }
    // softmax over g
    float m = fmaxf(fmaxf(v[0], v[1]), fmaxf(v[2], v[3]));
    float e[G_]; float s = 0.f;
    #pragma unroll
    for (int g = 0; g < G_; g++) { e[g] = expf(v[g] - m); s += e[g]; }
    float inv = 1.f / s;

    if (pos < 9) {
        float w = 0.f;
        #pragma unroll
        for (int g = 0; g < G_; g++) w = fmaf(e[g] * inv, w_k[(g * C_ + c) * 9 + pos], w);
        g_weight[(b * C_ + c) * 9 + pos] = w;
    } else {
        float bb = 0.f;
        #pragma unroll
        for (int g = 0; g < G_; g++) bb = fmaf(e[g] * inv, b_k[g * C_ + c], bb);
        g_bias[b * C_ + c] = bb;
    }
}

// ---------------------------------------------------------------------------
// Kernel 3: depthwise 3x3 conv, dynamic weights + bias, SAME pad.
// grid = (3 tiles, 1024 planes) x4 launches (bc_base). 256 threads.
// 32 output rows (+2 halo) per block; only halo is zeroed.
// ---------------------------------------------------------------------------
#define SW 104
#define TROWS 32
#define SROWS (TROWS+2)

__global__ __launch_bounds__(256) void conv_kernel(const float* __restrict__ x,
                                                   float* __restrict__ out,
                                                   int bc_base)
{
    __shared__ float s[SROWS * SW];
    int tile = blockIdx.x;
    int bc   = bc_base + blockIdx.y;
    int tid  = threadIdx.x;
    int r0   = tile * TROWS;
    const float4* xp4 = reinterpret_cast<const float4*>(x + (size_t)bc * PLANE);

    // halo-only zeroing: left col 3, right col 100 (all rows); top/bottom rows
    if (tid < SROWS) { s[tid * SW + 3] = 0.f; s[tid * SW + 100] = 0.f; }
    if (r0 == 0 && tid < 98) s[3 + tid] = 0.f;                       // smem row 0
    if (r0 + TROWS == H_ && tid < 98) s[(SROWS - 1) * SW + 3 + tid] = 0.f;

    // load rows r0-1 .. r0+32 -> smem rows 0..33, cols shifted by +4
    #pragma unroll
    for (int j = 0; j < 4; j++) {
        int idx = tid + j * 256;
        if (idx < SROWS * 24) {
            int sr = idx / 24;
            int c4 = idx % 24;
            int ir = r0 - 1 + sr;
            if (ir >= 0 && ir < H_) {
                float4 v = xp4[ir * 24 + c4];
                *reinterpret_cast<float4*>(&s[sr * SW + 4 + c4 * 4]) = v;
            }
        }
    }

    float w[9];
    #pragma unroll
    for (int i = 0; i < 9; i++) w[i] = __ldg(&g_weight[bc * 9 + i]);
    float bb = __ldg(&g_bias[bc]);
    __syncthreads();

    float* op = out + (size_t)bc * PLANE + (size_t)r0 * W_;
    #pragma unroll
    for (int j = 0; j < 3; j++) {
        int item = tid + j * 256;
        int r  = item / 24;
        int c0 = (item % 24) * 4;
        float o0 = bb, o1 = bb, o2 = bb, o3 = bb;
        #pragma unroll
        for (int k = 0; k < 3; k++) {
            int rb = (r + k) * SW + 4 + c0;
            float  l  = s[rb - 1];
            float4 m4 = *reinterpret_cast<const float4*>(&s[rb]);
            float  rr = s[rb + 4];
            float w0 = w[k * 3 + 0], w1v = w[k * 3 + 1], w2v = w[k * 3 + 2];
            o0 = fmaf(w0, l,    fmaf(w1v, m4.x, fmaf(w2v, m4.y, o0)));
            o1 = fmaf(w0, m4.x, fmaf(w1v, m4.y, fmaf(w2v, m4.z, o1)));
            o2 = fmaf(w0, m4.y, fmaf(w1v, m4.z, fmaf(w2v, m4.w, o2)));
            o3 = fmaf(w0, m4.z, fmaf(w1v, m4.w, fmaf(w2v, rr,   o3)));
        }
        *reinterpret_cast<float4*>(&op[r * W_ + c0]) = make_float4(o0, o1, o2, o3);
    }
}

// ---------------------------------------------------------------------------
// Launch. Inputs: x, w_k, b_k, w1, b1, bn_g, bn_b, bn_m, bn_v, w2, b2.
// ---------------------------------------------------------------------------
extern "C" void kernel_launch(void* const* d_in, const int* in_sizes, int n_in,
                              void* d_out, int out_size)
{
    const float* x    = (const float*)d_in[0];
    const float* w_k  = (const float*)d_in[1];
    const float* b_k  = (const float*)d_in[2];
    const float* w1   = (const float*)d_in[3];
    const float* b1   = (const float*)d_in[4];
    const float* bn_g = (const float*)d_in[5];
    const float* bn_b = (const float*)d_in[6];
    const float* bn_m = (const float*)d_in[7];
    const float* bn_v = (const float*)d_in[8];
    const float* w2   = (const float*)d_in[9];
    const float* b2   = (const float*)d_in[10];
    float* out = (float*)d_out;

    transpose_kernel<<<80, 256>>>(w1, w2);
    pool_kernel<<<BC, 256>>>(x);
    dim3 pg(10, B_);
    proj_kernel<<<pg, 256>>>(b1, bn_g, bn_b, bn_m, bn_v, b2, w_k, b_k);
    dim3 cg(3, BC / 4);
    for (int q = 0; q < 4; q++)
        conv_kernel<<<cg, 256>>>(x, out, q * (BC / 4));
}

// round 4
// speedup vs baseline: 1.6726x; 1.1670x over previous
#include <cuda_runtime.h>
#include <math.h>

#define B_  16
#define C_  256
#define H_  96
#define W_  96
#define G_  4
#define KK  3
#define RED 4
#define CH  (C_ / RED)        // 64
#define PLANE (H_ * W_)       // 9216
#define BC (B_ * C_)          // 4096

// Scratch (allocation-free rule -> __device__ globals)
__device__ float g_pooled[B_ * C_ * 9];
__device__ float g_gmean [B_ * C_];
__device__ float g_weight[B_ * C_ * 9];
__device__ float g_bias  [B_ * C_];
__device__ float g_w1t[C_ * CH];        // w1t[k][o] = w1[o][k]   (256 x 64)
__device__ float g_w2t[CH * C_ * G_];   // w2t[k][gc] = w2[gc][k] (64 x 1024)

// ---------------------------------------------------------------------------
// Kernel 1: pool (blocks 0..4095) + weight transpose (blocks 4096..4175).
// ---------------------------------------------------------------------------
__global__ __launch_bounds__(256) void pool_kernel(const float* __restrict__ x,
                                                   const float* __restrict__ w1,
                                                   const float* __restrict__ w2)
{
    int tid = threadIdx.x;
    if (blockIdx.x >= BC) {
        // transpose part
        int idx = (blockIdx.x - BC) * 256 + tid;
        if (idx < C_ * CH) {
            int k = idx / CH, o = idx % CH;
            g_w1t[idx] = w1[o * C_ + k];
        }
        for (int i = idx; i < CH * C_ * G_; i += 80 * 256) {
            int k = i / (C_ * G_), gc = i % (C_ * G_);
            g_w2t[i] = w2[gc * CH + k];
        }
        return;
    }

    int bc = blockIdx.x;
    const float4* xp = reinterpret_cast<const float4*>(x + (size_t)bc * PLANE);
    __shared__ float bins[9];
    if (tid < 9) bins[tid] = 0.f;
    __syncthreads();

    #pragma unroll
    for (int band = 0; band < 3; band++) {
        float a0 = 0.f, a1 = 0.f, a2 = 0.f;
        #pragma unroll
        for (int j = 0; j < 3; j++) {
            int idx = band * 768 + tid + j * 256;
            float4 v = xp[idx];
            float s = (v.x + v.y) + (v.z + v.w);
            int kx = (idx % 24) / 8;
            if (kx == 0) a0 += s; else if (kx == 1) a1 += s; else a2 += s;
        }
        #pragma unroll
        for (int o = 16; o > 0; o >>= 1) {
            a0 += __shfl_down_sync(0xffffffffu, a0, o);
            a1 += __shfl_down_sync(0xffffffffu, a1, o);
            a2 += __shfl_down_sync(0xffffffffu, a2, o);
        }
        if ((tid & 31) == 0) {
            atomicAdd(&bins[band * 3 + 0], a0);
            atomicAdd(&bins[band * 3 + 1], a1);
            atomicAdd(&bins[band * 3 + 2], a2);
        }
    }
    __syncthreads();
    if (tid < 9) g_pooled[bc * 9 + tid] = bins[tid] * (1.f / 1024.f);
    if (tid == 0) {
        float t = 0.f;
        #pragma unroll
        for (int i = 0; i < 9; i++) t += bins[i];
        g_gmean[bc] = t * (1.f / (float)PLANE);
    }
}

// ---------------------------------------------------------------------------
// Kernel 2: proj + softmax + mixdown (coalesced transposed weights).
// grid = (10 positions, B). 256 threads (one per channel c).
// ---------------------------------------------------------------------------
__global__ __launch_bounds__(256) void proj_kernel(
    const float* __restrict__ b1,
    const float* __restrict__ bn_g, const float* __restrict__ bn_b,
    const float* __restrict__ bn_m, const float* __restrict__ bn_v,
    const float* __restrict__ b2,
    const float* __restrict__ w_k, const float* __restrict__ b_k)
{
    int pos = blockIdx.x;   // 0..9
    int b   = blockIdx.y;   // 0..15
    int tid = threadIdx.x;
    int c   = tid;

    __shared__ float t_s[C_];
    __shared__ float hpart[4][CH];
    __shared__ float h_s[CH];

    t_s[c] = (pos < 9) ? g_pooled[(b * C_ + c) * 9 + pos] : g_gmean[b * C_ + c];
    __syncthreads();

    {
        int o = tid & 63, part = tid >> 6;
        const float* wt = g_w1t + part * 64 * CH + o;
        const float* ts = t_s + part * 64;
        float acc = 0.f;
        #pragma unroll 8
        for (int k = 0; k < 64; k++) acc = fmaf(wt[k * CH], ts[k], acc);
        hpart[part][o] = acc;
    }
    __syncthreads();
    if (tid < CH) {
        float h = hpart[0][tid] + hpart[1][tid] + hpart[2][tid] + hpart[3][tid] + b1[tid];
        h = (h - bn_m[tid]) * (bn_g[tid] * rsqrtf(bn_v[tid] + 1e-5f)) + bn_b[tid];
        h = 0.5f * h * (1.0f + erff(h * 0.70710678118654752f));
        h_s[tid] = h;
    }
    __syncthreads();

    float v[G_];
    #pragma unroll
    for (int g = 0; g < G_; g++) v[g] = b2[g * C_ + c];
    #pragma unroll 8
    for (int k = 0; k < CH; k++) {
        float h = h_s[k];
        const float* row = g_w2t + (size_t)k * (C_ * G_) + c;
        #pragma unroll
        for (int g = 0; g < G_; g++) v[g] = fmaf(row[g * C_], h, v[g]);
    }
    float m = fmaxf(fmaxf(v[0], v[1]), fmaxf(v[2], v[3]));
    float e[G_]; float s = 0.f;
    #pragma unroll
    for (int g = 0; g < G_; g++) { e[g] = expf(v[g] - m); s += e[g]; }
    float inv = 1.f / s;

    if (pos < 9) {
        float w = 0.f;
        #pragma unroll
        for (int g = 0; g < G_; g++) w = fmaf(e[g] * inv, w_k[(g * C_ + c) * 9 + pos], w);
        g_weight[(b * C_ + c) * 9 + pos] = w;
    } else {
        float bb = 0.f;
        #pragma unroll
        for (int g = 0; g < G_; g++) bb = fmaf(e[g] * inv, b_k[g * C_ + c], bb);
        g_bias[b * C_ + c] = bb;
    }
}

// ---------------------------------------------------------------------------
// Kernel 3: depthwise 3x3 conv, register-blocked 4 rows x 4 cols per thread.
// Tile = 48 output rows (+2 halo) of one (b,c) plane; 288 threads
// (12 row-groups x 24 col-groups). Rolling 3-row register window.
// ---------------------------------------------------------------------------
#define SW 104
#define TROWS 48
#define SROWS (TROWS + 2)   // 50

__global__ __launch_bounds__(288) void conv_kernel(const float* __restrict__ x,
                                                   float* __restrict__ out,
                                                   int bc_base)
{
    __shared__ float s[SROWS * SW];   // 20.8 KB
    int tile = blockIdx.x;            // 0..1
    int bc   = bc_base + blockIdx.y;
    int tid  = threadIdx.x;
    int r0   = tile * TROWS;
    const float4* xp4 = reinterpret_cast<const float4*>(x + (size_t)bc * PLANE);

    // halo zeroing: left col 3 / right col 100 all rows; top/bottom halo rows
    if (tid < SROWS) { s[tid * SW + 3] = 0.f; s[tid * SW + 100] = 0.f; }
    if (tile == 0 && tid < 98) s[3 + tid] = 0.f;                        // sr=0
    if (tile == 1 && tid < 98) s[(SROWS - 1) * SW + 3 + tid] = 0.f;     // sr=49

    // load rows r0-1 .. r0+48 -> smem rows 0..49 (50 rows x 24 float4 = 1200)
    #pragma unroll
    for (int j = 0; j < 5; j++) {
        int idx = tid + j * 288;
        if (idx < SROWS * 24) {
            int sr = idx / 24;
            int c4 = idx % 24;
            int ir = r0 - 1 + sr;
            if (ir >= 0 && ir < H_) {
                float4 v = xp4[ir * 24 + c4];
                *reinterpret_cast<float4*>(&s[sr * SW + 4 + c4 * 4]) = v;
            }
        }
    }

    float w[9];
    #pragma unroll
    for (int i = 0; i < 9; i++) w[i] = __ldg(&g_weight[bc * 9 + i]);
    float bb = __ldg(&g_bias[bc]);
    __syncthreads();

    int r_g = tid / 24;          // 0..11
    int c0  = (tid % 24) * 4;
    int rb0 = r_g * 4;           // smem row of top halo for this thread's rows
    float* op = out + (size_t)bc * PLANE + (size_t)(r0 + r_g * 4) * W_ + c0;

    // rolling window registers: rows rb0 .. rb0+5
    float  la[3], ra[3];
    float4 ma[3];
    #pragma unroll
    for (int k = 0; k < 3; k++) {
        int rb = (rb0 + k) * SW + 4 + c0;
        la[k] = s[rb - 1];
        ma[k] = *reinterpret_cast<const float4*>(&s[rb]);
        ra[k] = s[rb + 4];
    }

    #pragma unroll
    for (int i = 0; i < 4; i++) {
        float o0 = bb, o1 = bb, o2 = bb, o3 = bb;
        #pragma unroll
        for (int k = 0; k < 3; k++) {
            float w0 = w[k * 3 + 0], w1v = w[k * 3 + 1], w2v = w[k * 3 + 2];
            float  l  = la[k];
            float4 m4 = ma[k];
            float  rr = ra[k];
            o0 = fmaf(w0, l,    fmaf(w1v, m4.x, fmaf(w2v, m4.y, o0)));
            o1 = fmaf(w0, m4.x, fmaf(w1v, m4.y, fmaf(w2v, m4.z, o1)));
            o2 = fmaf(w0, m4.y, fmaf(w1v, m4.z, fmaf(w2v, m4.w, o2)));
            o3 = fmaf(w0, m4.z, fmaf(w1v, m4.w, fmaf(w2v, rr,   o3)));
        }
        *reinterpret_cast<float4*>(op + (size_t)i * W_) = make_float4(o0, o1, o2, o3);
        if (i < 3) {  // slide window down one row
            la[0] = la[1]; ma[0] = ma[1]; ra[0] = ra[1];
            la[1] = la[2]; ma[1] = ma[2]; ra[1] = ra[2];
            int rb = (rb0 + 3 + i) * SW + 4 + c0;
            la[2] = s[rb - 1];
            ma[2] = *reinterpret_cast<const float4*>(&s[rb]);
            ra[2] = s[rb + 4];
        }
    }
}

// ---------------------------------------------------------------------------
// Launch. Inputs: x, w_k, b_k, w1, b1, bn_g, bn_b, bn_m, bn_v, w2, b2.
// ---------------------------------------------------------------------------
extern "C" void kernel_launch(void* const* d_in, const int* in_sizes, int n_in,
                              void* d_out, int out_size)
{
    const float* x    = (const float*)d_in[0];
    const float* w_k  = (const float*)d_in[1];
    const float* b_k  = (const float*)d_in[2];
    const float* w1   = (const float*)d_in[3];
    const float* b1   = (const float*)d_in[4];
    const float* bn_g = (const float*)d_in[5];
    const float* bn_b = (const float*)d_in[6];
    const float* bn_m = (const float*)d_in[7];
    const float* bn_v = (const float*)d_in[8];
    const float* w2   = (const float*)d_in[9];
    const float* b2   = (const float*)d_in[10];
    float* out = (float*)d_out;

    pool_kernel<<<BC + 80, 256>>>(x, w1, w2);
    dim3 pg(10, B_);
    proj_kernel<<<pg, 256>>>(b1, bn_g, bn_b, bn_m, bn_v, b2, w_k, b_k);
    dim3 cg(2, BC / 4);
    for (int q = 0; q < 4; q++)
        conv_kernel<<<cg, 288>>>(x, out, q * (BC / 4));
}

// round 5
// speedup vs baseline: 1.9909x; 1.1903x over previous
#include <cuda_runtime.h>
#include <math.h>

#define B_  16
#define C_  256
#define H_  96
#define W_  96
#define G_  4
#define KK  3
#define RED 4
#define CH  (C_ / RED)        // 64
#define PLANE (H_ * W_)       // 9216
#define BC (B_ * C_)          // 4096

// Scratch (allocation-free rule -> __device__ globals)
__device__ float g_pooled[B_ * C_ * 9];
__device__ float g_gmean [B_ * C_];
__device__ float g_weight[B_ * C_ * 9];
__device__ float g_bias  [B_ * C_];
__device__ float g_w1t[C_ * CH];        // w1t[k][o] = w1[o][k]   (256 x 64)
__device__ float g_w2t[CH * C_ * G_];   // w2t[k][gc] = w2[gc][k] (64 x 1024)

// ---------------------------------------------------------------------------
// Kernel 1: pool (blocks 0..4095) + weight transpose (blocks 4096..4175).
// ---------------------------------------------------------------------------
__global__ __launch_bounds__(256) void pool_kernel(const float* __restrict__ x,
                                                   const float* __restrict__ w1,
                                                   const float* __restrict__ w2)
{
    int tid = threadIdx.x;
    if (blockIdx.x >= BC) {
        int idx = (blockIdx.x - BC) * 256 + tid;
        if (idx < C_ * CH) {
            int k = idx / CH, o = idx % CH;
            g_w1t[idx] = w1[o * C_ + k];
        }
        for (int i = idx; i < CH * C_ * G_; i += 80 * 256) {
            int k = i / (C_ * G_), gc = i % (C_ * G_);
            g_w2t[i] = w2[gc * CH + k];
        }
        return;
    }

    int bc = blockIdx.x;
    const float4* xp = reinterpret_cast<const float4*>(x + (size_t)bc * PLANE);
    __shared__ float bins[9];
    if (tid < 9) bins[tid] = 0.f;
    __syncthreads();

    #pragma unroll
    for (int band = 0; band < 3; band++) {
        float a0 = 0.f, a1 = 0.f, a2 = 0.f;
        #pragma unroll
        for (int j = 0; j < 3; j++) {
            int idx = band * 768 + tid + j * 256;
            float4 v = xp[idx];
            float s = (v.x + v.y) + (v.z + v.w);
            int kx = (idx % 24) / 8;
            if (kx == 0) a0 += s; else if (kx == 1) a1 += s; else a2 += s;
        }
        #pragma unroll
        for (int o = 16; o > 0; o >>= 1) {
            a0 += __shfl_down_sync(0xffffffffu, a0, o);
            a1 += __shfl_down_sync(0xffffffffu, a1, o);
            a2 += __shfl_down_sync(0xffffffffu, a2, o);
        }
        if ((tid & 31) == 0) {
            atomicAdd(&bins[band * 3 + 0], a0);
            atomicAdd(&bins[band * 3 + 1], a1);
            atomicAdd(&bins[band * 3 + 2], a2);
        }
    }
    __syncthreads();
    if (tid < 9) g_pooled[bc * 9 + tid] = bins[tid] * (1.f / 1024.f);
    if (tid == 0) {
        float t = 0.f;
        #pragma unroll
        for (int i = 0; i < 9; i++) t += bins[i];
        g_gmean[bc] = t * (1.f / (float)PLANE);
    }
}

// ---------------------------------------------------------------------------
// Kernel 2: proj + softmax + mixdown (coalesced transposed weights).
// ---------------------------------------------------------------------------
__global__ __launch_bounds__(256) void proj_kernel(
    const float* __restrict__ b1,
    const float* __restrict__ bn_g, const float* __restrict__ bn_b,
    const float* __restrict__ bn_m, const float* __restrict__ bn_v,
    const float* __restrict__ b2,
    const float* __restrict__ w_k, const float* __restrict__ b_k)
{
    int pos = blockIdx.x;
    int b   = blockIdx.y;
    int tid = threadIdx.x;
    int c   = tid;

    __shared__ float t_s[C_];
    __shared__ float hpart[4][CH];
    __shared__ float h_s[CH];

    t_s[c] = (pos < 9) ? g_pooled[(b * C_ + c) * 9 + pos] : g_gmean[b * C_ + c];
    __syncthreads();

    {
        int o = tid & 63, part = tid >> 6;
        const float* wt = g_w1t + part * 64 * CH + o;
        const float* ts = t_s + part * 64;
        float acc = 0.f;
        #pragma unroll 8
        for (int k = 0; k < 64; k++) acc = fmaf(wt[k * CH], ts[k], acc);
        hpart[part][o] = acc;
    }
    __syncthreads();
    if (tid < CH) {
        float h = hpart[0][tid] + hpart[1][tid] + hpart[2][tid] + hpart[3][tid] + b1[tid];
        h = (h - bn_m[tid]) * (bn_g[tid] * rsqrtf(bn_v[tid] + 1e-5f)) + bn_b[tid];
        h = 0.5f * h * (1.0f + erff(h * 0.70710678118654752f));
        h_s[tid] = h;
    }
    __syncthreads();

    float v[G_];
    #pragma unroll
    for (int g = 0; g < G_; g++) v[g] = b2[g * C_ + c];
    #pragma unroll 8
    for (int k = 0; k < CH; k++) {
        float h = h_s[k];
        const float* row = g_w2t + (size_t)k * (C_ * G_) + c;
        #pragma unroll
        for (int g = 0; g < G_; g++) v[g] = fmaf(row[g * C_], h, v[g]);
    }
    float m = fmaxf(fmaxf(v[0], v[1]), fmaxf(v[2], v[3]));
    float e[G_]; float s = 0.f;
    #pragma unroll
    for (int g = 0; g < G_; g++) { e[g] = expf(v[g] - m); s += e[g]; }
    float inv = 1.f / s;

    if (pos < 9) {
        float w = 0.f;
        #pragma unroll
        for (int g = 0; g < G_; g++) w = fmaf(e[g] * inv, w_k[(g * C_ + c) * 9 + pos], w);
        g_weight[(b * C_ + c) * 9 + pos] = w;
    } else {
        float bb = 0.f;
        #pragma unroll
        for (int g = 0; g < G_; g++) bb = fmaf(e[g] * inv, b_k[g * C_ + c], bb);
        g_bias[b * C_ + c] = bb;
    }
}

// ---------------------------------------------------------------------------
// Kernel 3: depthwise 3x3 conv, DIRECT-LDG register-rolling version.
// No smem, no syncs. One CTA per (b,c) plane; 288 threads = 12 row-groups
// (8 output rows each) x 24 col-groups (4 cols each). Rolling 3-row window.
// Overlap rows + scalar edges are L1 hits; DRAM traffic = one x read + write.
// ---------------------------------------------------------------------------
__device__ __forceinline__ void ld_row(const float* __restrict__ xp, int ir, int c0,
                                       float& l, float4& m, float& r)
{
    if (ir >= 0 && ir < H_) {
        const float* row = xp + ir * W_;
        m = *reinterpret_cast<const float4*>(row + c0);
        l = (c0 > 0)  ? __ldg(row + c0 - 1) : 0.f;
        r = (c0 < 92) ? __ldg(row + c0 + 4) : 0.f;
    } else {
        m = make_float4(0.f, 0.f, 0.f, 0.f);
        l = 0.f; r = 0.f;
    }
}

__global__ __launch_bounds__(288) void conv_kernel(const float* __restrict__ x,
                                                   float* __restrict__ out)
{
    int bc  = blockIdx.x;
    int tid = threadIdx.x;
    int r_g = tid / 24;            // 0..11
    int c0  = (tid % 24) * 4;      // 0..92
    const float* xp = x + (size_t)bc * PLANE;

    float w[9];
    #pragma unroll
    for (int i = 0; i < 9; i++) w[i] = __ldg(&g_weight[bc * 9 + i]);
    float bb = __ldg(&g_bias[bc]);

    int rbase = r_g * 8;
    float  l0, l1, r0, r1;
    float4 m0, m1;
    ld_row(xp, rbase - 1, c0, l0, m0, r0);
    ld_row(xp, rbase,     c0, l1, m1, r1);

    float* op = out + (size_t)bc * PLANE + (size_t)rbase * W_ + c0;

    #pragma unroll
    for (int i = 0; i < 8; i++) {
        float  l2; float4 m2; float r2;
        ld_row(xp, rbase + i + 1, c0, l2, m2, r2);   // issue next row early

        float o0 = bb, o1 = bb, o2 = bb, o3 = bb;
        // row 0 of window
        o0 = fmaf(w[0], l0,   fmaf(w[1], m0.x, fmaf(w[2], m0.y, o0)));
        o1 = fmaf(w[0], m0.x, fmaf(w[1], m0.y, fmaf(w[2], m0.z, o1)));
        o2 = fmaf(w[0], m0.y, fmaf(w[1], m0.z, fmaf(w[2], m0.w, o2)));
        o3 = fmaf(w[0], m0.z, fmaf(w[1], m0.w, fmaf(w[2], r0,   o3)));
        // row 1
        o0 = fmaf(w[3], l1,   fmaf(w[4], m1.x, fmaf(w[5], m1.y, o0)));
        o1 = fmaf(w[3], m1.x, fmaf(w[4], m1.y, fmaf(w[5], m1.z, o1)));
        o2 = fmaf(w[3], m1.y, fmaf(w[4], m1.z, fmaf(w[5], m1.w, o2)));
        o3 = fmaf(w[3], m1.z, fmaf(w[4], m1.w, fmaf(w[5], r1,   o3)));
        // row 2
        o0 = fmaf(w[6], l2,   fmaf(w[7], m2.x, fmaf(w[8], m2.y, o0)));
        o1 = fmaf(w[6], m2.x, fmaf(w[7], m2.y, fmaf(w[8], m2.z, o1)));
        o2 = fmaf(w[6], m2.y, fmaf(w[7], m2.z, fmaf(w[8], m2.w, o2)));
        o3 = fmaf(w[6], m2.z, fmaf(w[7], m2.w, fmaf(w[8], r2,   o3)));

        *reinterpret_cast<float4*>(op + (size_t)i * W_) = make_float4(o0, o1, o2, o3);

        l0 = l1; m0 = m1; r0 = r1;
        l1 = l2; m1 = m2; r1 = r2;
    }
}

// ---------------------------------------------------------------------------
// Launch. Inputs: x, w_k, b_k, w1, b1, bn_g, bn_b, bn_m, bn_v, w2, b2.
// ---------------------------------------------------------------------------
extern "C" void kernel_launch(void* const* d_in, const int* in_sizes, int n_in,
                              void* d_out, int out_size)
{
    const float* x    = (const float*)d_in[0];
    const float* w_k  = (const float*)d_in[1];
    const float* b_k  = (const float*)d_in[2];
    const float* w1   = (const float*)d_in[3];
    const float* b1   = (const float*)d_in[4];
    const float* bn_g = (const float*)d_in[5];
    const float* bn_b = (const float*)d_in[6];
    const float* bn_m = (const float*)d_in[7];
    const float* bn_v = (const float*)d_in[8];
    const float* w2   = (const float*)d_in[9];
    const float* b2   = (const float*)d_in[10];
    float* out = (float*)d_out;

    pool_kernel<<<BC + 80, 256>>>(x, w1, w2);
    dim3 pg(10, B_);
    proj_kernel<<<pg, 256>>>(b1, bn_g, bn_b, bn_m, bn_v, b2, w_k, b_k);
    conv_kernel<<<BC, 288>>>(x, out);
}